// round 1
// baseline (speedup 1.0000x reference)
#include <cuda_runtime.h>

#define D       256
#define KCODES  1024
#define BM      128
#define BN      128
#define BD      32
#define LDA     129   // BM + 1 padding

// ---- scratch (no allocations allowed) ----
__device__ float  g_z_norm[131072];
__device__ float  g_e_half[KCODES];
__device__ float  g_counts[KCODES];
__device__ double g_loss;

// ---------------------------------------------------------------------------
__global__ void init_kernel() {
    int t = threadIdx.x;
    if (t < KCODES) g_counts[t] = 0.0f;
    if (t == 0)     g_loss = 0.0;
}

// One warp per row: ||z_n||^2 for n < N, 0.5*||e_k||^2 for the K codebook rows.
__global__ void norms_kernel(const float* __restrict__ z,
                             const float* __restrict__ e, int N) {
    int gw   = (blockIdx.x * blockDim.x + threadIdx.x) >> 5;
    int lane = threadIdx.x & 31;
    int total = N + KCODES;
    if (gw >= total) return;
    const float4* src = (const float4*)((gw < N) ? (z + (size_t)gw * D)
                                                 : (e + (size_t)(gw - N) * D));
    float4 a = src[lane];
    float4 b = src[lane + 32];
    float s = a.x*a.x + a.y*a.y + a.z*a.z + a.w*a.w
            + b.x*b.x + b.y*b.y + b.z*b.z + b.w*b.w;
    #pragma unroll
    for (int o = 16; o > 0; o >>= 1) s += __shfl_down_sync(0xffffffffu, s, o);
    if (lane == 0) {
        if (gw < N) g_z_norm[gw] = s;
        else        g_e_half[gw - N] = 0.5f * s;
    }
}

// ---------------------------------------------------------------------------
struct ComputeSmem {
    float As[BD][LDA];
    float Bs[BD][LDA];
    float eh[BN];
};
struct ReduceSmem {
    float rv[BM][16];
    int   ri[BM][16];
    float dv[BM];
    int   idx[BM];
};
union SmemU { ComputeSmem c; ReduceSmem r; };

// Block: 128 rows of z vs all 1024 codes. 256 threads (16x16), 8x8 micro-tile,
// stride-16 row/col mapping. Running argmin in registers, then gather.
__global__ __launch_bounds__(256) void vq_main(const float* __restrict__ z,
                                               const float* __restrict__ e,
                                               float* __restrict__ outq, int N) {
    __shared__ SmemU sm;
    const int tid = threadIdx.x;
    const int tx = tid & 15;
    const int ty = tid >> 4;
    const int rowbase = blockIdx.x * BM;

    float minv[8];
    int   mini[8];
    #pragma unroll
    for (int i = 0; i < 8; ++i) { minv[i] = __int_as_float(0x7f800000); mini[i] = 0; }

    #pragma unroll 1
    for (int kt = 0; kt < KCODES; kt += BN) {
        __syncthreads();                       // protect eh from previous epilogue
        if (tid < BN) sm.c.eh[tid] = g_e_half[kt + tid];

        float acc[8][8];
        #pragma unroll
        for (int i = 0; i < 8; ++i)
            #pragma unroll
            for (int j = 0; j < 8; ++j) acc[i][j] = 0.0f;

        #pragma unroll 1
        for (int d0 = 0; d0 < D; d0 += BD) {
            __syncthreads();
            // load A (z rows) and B (codes) chunks, transposed into SMEM
            #pragma unroll
            for (int it = 0; it < 4; ++it) {
                int id = tid + it * 256;
                int r  = id >> 3;          // 0..127
                int c4 = id & 7;           // 0..7  (float4 within 32-col chunk)
                float4 v = *(const float4*)(z + (size_t)(rowbase + r) * D + d0 + c4 * 4);
                sm.c.As[c4*4+0][r] = v.x;
                sm.c.As[c4*4+1][r] = v.y;
                sm.c.As[c4*4+2][r] = v.z;
                sm.c.As[c4*4+3][r] = v.w;
                float4 w = *(const float4*)(e + (size_t)(kt + r) * D + d0 + c4 * 4);
                sm.c.Bs[c4*4+0][r] = w.x;
                sm.c.Bs[c4*4+1][r] = w.y;
                sm.c.Bs[c4*4+2][r] = w.z;
                sm.c.Bs[c4*4+3][r] = w.w;
            }
            __syncthreads();

            #pragma unroll 8
            for (int kk = 0; kk < BD; ++kk) {
                float a[8], b[8];
                #pragma unroll
                for (int i = 0; i < 8; ++i) a[i] = sm.c.As[kk][ty + 16 * i];
                #pragma unroll
                for (int j = 0; j < 8; ++j) b[j] = sm.c.Bs[kk][tx + 16 * j];
                #pragma unroll
                for (int i = 0; i < 8; ++i)
                    #pragma unroll
                    for (int j = 0; j < 8; ++j)
                        acc[i][j] += a[i] * b[j];
            }
        }

        // epilogue: score = 0.5*||e||^2 - z.e ; update running argmin
        #pragma unroll
        for (int j = 0; j < 8; ++j) {
            float ehv = sm.c.eh[tx + 16 * j];
            int   col = kt + tx + 16 * j;
            #pragma unroll
            for (int i = 0; i < 8; ++i) {
                float s = ehv - acc[i][j];
                if (s < minv[i]) { minv[i] = s; mini[i] = col; }
            }
        }
    }

    __syncthreads();   // done with compute SMEM; switch union to reduce view
    #pragma unroll
    for (int i = 0; i < 8; ++i) {
        int r = ty + 16 * i;
        sm.r.rv[r][tx] = minv[i];
        sm.r.ri[r][tx] = mini[i];
    }
    __syncthreads();

    if (tid < BM) {
        float bv = sm.r.rv[tid][0];
        int   bi = sm.r.ri[tid][0];
        #pragma unroll
        for (int t = 1; t < 16; ++t) {
            float v  = sm.r.rv[tid][t];
            int   ix = sm.r.ri[tid][t];
            if (v < bv || (v == bv && ix < bi)) { bv = v; bi = ix; }
        }
        sm.r.idx[tid] = bi;
        sm.r.dv[tid]  = g_z_norm[rowbase + tid] + 2.0f * bv;  // ||z - e||^2
        atomicAdd(&g_counts[bi], 1.0f);
    }
    __syncthreads();

    // block loss reduction (128 values)
    if (tid < 64) sm.r.dv[tid] += sm.r.dv[tid + 64];
    __syncthreads();
    if (tid < 32) {
        float v = sm.r.dv[tid] + sm.r.dv[tid + 32];
        #pragma unroll
        for (int o = 16; o > 0; o >>= 1) v += __shfl_down_sync(0xffffffffu, v, o);
        if (tid == 0) atomicAdd(&g_loss, (double)v);
    }
    __syncthreads();

    // gather quantized rows to output (scalar stores: out base is +1 float,
    // so float4 would be misaligned; coalesced 32-bit stores are BW-full)
    #pragma unroll 1
    for (int p = tid; p < BM * D; p += 256) {
        int r = p >> 8;
        int c = p & 255;
        outq[(size_t)(rowbase + r) * D + c] = e[(size_t)sm.r.idx[r] * D + c];
    }
}

// ---------------------------------------------------------------------------
__global__ void finalize_kernel(float* __restrict__ out, int N) {
    __shared__ float red[1024];
    int t = threadIdx.x;
    float p = g_counts[t] * (1.0f / (float)N);
    red[t] = p * logf(p + 1e-10f);
    __syncthreads();
    for (int o = 512; o > 0; o >>= 1) {
        if (t < o) red[t] += red[t + o];
        __syncthreads();
    }
    if (t == 0) {
        out[0] = 0.25f * (float)(g_loss / ((double)N * (double)D));
        out[(size_t)N * D + 1] = expf(-red[0]);
    }
}

// ---------------------------------------------------------------------------
extern "C" void kernel_launch(void* const* d_in, const int* in_sizes, int n_in,
                              void* d_out, int out_size) {
    const float* z = (const float*)d_in[0];   // z_e  [N, 256]
    const float* e = (const float*)d_in[1];   // emb  [1024, 256]
    float* out = (float*)d_out;               // [loss, quantized(N*256), perplexity]
    int N = in_sizes[0] / D;                  // 131072

    init_kernel<<<1, 1024>>>();
    int warps  = N + KCODES;
    int blocks = (warps * 32 + 255) / 256;
    norms_kernel<<<blocks, 256>>>(z, e, N);
    vq_main<<<N / BM, 256>>>(z, e, out + 1, N);
    finalize_kernel<<<1, 1024>>>(out, N);
}